// round 4
// baseline (speedup 1.0000x reference)
#include <cuda_runtime.h>
#include <math.h>

#define NN 100000
#define EE 1600000
#define KC 128      // IN_C and HID (both 128)
#define HIDC 128
#define OC 64

// ---- device scratch (no allocations allowed) ----
__device__ int   g_deg[NN];
__device__ float g_dinv[NN];
__device__ int   g_colptr[NN + 1];
__device__ int   g_fill[NN];
__device__ int   g_srcv[EE];
__device__ float g_wv[EE];
__device__ float g_h [(size_t)NN * HIDC];  // x @ W1
__device__ float g_a [(size_t)NN * HIDC];  // relu(agg1 + b1)
__device__ float g_h2[(size_t)NN * OC];    // g_a @ W2
__device__ int   g_is64;

// ---- dtype detection: int64 edge_index has zero high words (values < 2^31) ----
__global__ void k_detect(const int* __restrict__ ei32) {
    __shared__ int nz;
    if (threadIdx.x == 0) nz = 0;
    __syncthreads();
    for (int i = threadIdx.x; i < 4096; i += blockDim.x) {
        if (ei32[2 * i + 1] != 0) nz = 1;  // benign race
    }
    __syncthreads();
    if (threadIdx.x == 0) g_is64 = nz ? 0 : 1;
}

__device__ __forceinline__ int edge_at(const void* ei, size_t idx, int is64) {
    if (is64) return (int)((const long long*)ei)[idx];
    return ((const int*)ei)[idx];
}

__global__ void k_zero_deg() {
    int i = blockIdx.x * blockDim.x + threadIdx.x;
    if (i < NN) g_deg[i] = 0;
}

__global__ void k_count(const void* __restrict__ ei) {
    int e = blockIdx.x * blockDim.x + threadIdx.x;
    if (e >= EE) return;
    int is64 = g_is64;
    int c = edge_at(ei, (size_t)EE + e, is64);
    atomicAdd(&g_deg[c], 1);
}

__global__ void k_dinv() {
    int i = blockIdx.x * blockDim.x + threadIdx.x;
    if (i < NN) {
        int d = g_deg[i];
        g_dinv[i] = (d > 0) ? 1.0f / sqrtf((float)d) : 0.0f;
    }
}

// single-block exclusive scan of g_deg -> g_colptr / g_fill
__global__ void k_scan() {
    __shared__ int sh[1024];
    const int T = 1024;
    const int CH = (NN + T - 1) / T;  // 98
    int t = threadIdx.x;
    int lo = t * CH;
    int hi = min(lo + CH, NN);
    int s = 0;
    for (int i = lo; i < hi; i++) s += g_deg[i];
    sh[t] = s;
    __syncthreads();
    for (int off = 1; off < T; off <<= 1) {
        int v = 0;
        if (t >= off) v = sh[t - off];
        __syncthreads();
        if (t >= off) sh[t] += v;
        __syncthreads();
    }
    int run = sh[t] - s;  // exclusive prefix
    for (int i = lo; i < hi; i++) {
        g_colptr[i] = run;
        g_fill[i]   = run;
        run += g_deg[i];
    }
    if (t == T - 1) g_colptr[NN] = sh[T - 1];
}

__global__ void k_build(const void* __restrict__ ei) {
    int e = blockIdx.x * blockDim.x + threadIdx.x;
    if (e >= EE) return;
    int is64 = g_is64;
    int r = edge_at(ei, (size_t)e, is64);
    int c = edge_at(ei, (size_t)EE + e, is64);
    float w = g_dinv[r] * g_dinv[c];
    int pos = atomicAdd(&g_fill[c], 1);
    g_srcv[pos] = r;
    g_wv[pos]   = w;
}

// ---- SGEMM: Y[NN,OUTC] = X[NN,128] @ W[128,OUTC], 64x64 tile, 4x4/thread ----
template <int OUTC>
__global__ __launch_bounds__(256) void k_gemm(const float* __restrict__ X,
                                              const float* __restrict__ W,
                                              float* __restrict__ Y) {
    __shared__ float xs[64 * 64];  // xs[kk*64 + r]
    __shared__ float ws[64 * 64];  // ws[kk*64 + c]
    int row0 = blockIdx.x * 64;
    int col0 = blockIdx.y * 64;
    int tid  = threadIdx.x;
    int tr = (tid >> 4) << 2;   // 0..60
    int tc = (tid & 15) << 2;   // 0..60
    float acc[4][4] = {};

    for (int kb = 0; kb < KC; kb += 64) {
        // load W chunk: consecutive tid -> consecutive c (coalesced)
        for (int i = tid; i < 4096; i += 256) {
            int c = i & 63, kk = i >> 6;
            ws[kk * 64 + c] = W[(size_t)(kb + kk) * OUTC + col0 + c];
        }
        // load X chunk transposed: consecutive tid -> consecutive kk (coalesced)
        for (int i = tid; i < 4096; i += 256) {
            int kk = i & 63, r = i >> 6;
            int gr = row0 + r;
            xs[kk * 64 + r] = (gr < NN) ? X[(size_t)gr * KC + kb + kk] : 0.0f;
        }
        __syncthreads();
#pragma unroll 16
        for (int kk = 0; kk < 64; kk++) {
            float4 xv = *(const float4*)&xs[kk * 64 + tr];
            float4 wv = *(const float4*)&ws[kk * 64 + tc];
            acc[0][0] = fmaf(xv.x, wv.x, acc[0][0]);
            acc[0][1] = fmaf(xv.x, wv.y, acc[0][1]);
            acc[0][2] = fmaf(xv.x, wv.z, acc[0][2]);
            acc[0][3] = fmaf(xv.x, wv.w, acc[0][3]);
            acc[1][0] = fmaf(xv.y, wv.x, acc[1][0]);
            acc[1][1] = fmaf(xv.y, wv.y, acc[1][1]);
            acc[1][2] = fmaf(xv.y, wv.z, acc[1][2]);
            acc[1][3] = fmaf(xv.y, wv.w, acc[1][3]);
            acc[2][0] = fmaf(xv.z, wv.x, acc[2][0]);
            acc[2][1] = fmaf(xv.z, wv.y, acc[2][1]);
            acc[2][2] = fmaf(xv.z, wv.z, acc[2][2]);
            acc[2][3] = fmaf(xv.z, wv.w, acc[2][3]);
            acc[3][0] = fmaf(xv.w, wv.x, acc[3][0]);
            acc[3][1] = fmaf(xv.w, wv.y, acc[3][1]);
            acc[3][2] = fmaf(xv.w, wv.z, acc[3][2]);
            acc[3][3] = fmaf(xv.w, wv.w, acc[3][3]);
        }
        __syncthreads();
    }
    for (int i = 0; i < 4; i++) {
        int gr = row0 + tr + i;
        if (gr < NN) {
            float4 o = make_float4(acc[i][0], acc[i][1], acc[i][2], acc[i][3]);
            *(float4*)&Y[(size_t)gr * OUTC + col0 + tc] = o;
        }
    }
}

// ---- aggregation conv1: warp per node, 128 channels (float4/lane), +b1, relu ----
__global__ __launch_bounds__(256) void k_agg1(const float* __restrict__ b) {
    int gw   = (blockIdx.x * blockDim.x + threadIdx.x) >> 5;
    int lane = threadIdx.x & 31;
    if (gw >= NN) return;
    int s0 = g_colptr[gw], s1 = g_colptr[gw + 1];
    const float4* h4 = (const float4*)g_h;
    float4 acc = make_float4(0.f, 0.f, 0.f, 0.f);
    for (int e = s0; e < s1; e++) {
        int   s = g_srcv[e];   // uniform across warp (broadcast)
        float w = g_wv[e];
        float4 hv = h4[(size_t)s * 32 + lane];
        acc.x = fmaf(hv.x, w, acc.x);
        acc.y = fmaf(hv.y, w, acc.y);
        acc.z = fmaf(hv.z, w, acc.z);
        acc.w = fmaf(hv.w, w, acc.w);
    }
    float4 bv = ((const float4*)b)[lane];
    acc.x = fmaxf(acc.x + bv.x, 0.f);
    acc.y = fmaxf(acc.y + bv.y, 0.f);
    acc.z = fmaxf(acc.z + bv.z, 0.f);
    acc.w = fmaxf(acc.w + bv.w, 0.f);
    ((float4*)g_a)[(size_t)gw * 32 + lane] = acc;
}

// ---- aggregation conv2: warp per node, 64 channels (float2/lane), +b2 ----
__global__ __launch_bounds__(256) void k_agg2(const float* __restrict__ b,
                                              float* __restrict__ out) {
    int gw   = (blockIdx.x * blockDim.x + threadIdx.x) >> 5;
    int lane = threadIdx.x & 31;
    if (gw >= NN) return;
    int s0 = g_colptr[gw], s1 = g_colptr[gw + 1];
    const float2* h2 = (const float2*)g_h2;
    float2 acc = make_float2(0.f, 0.f);
    for (int e = s0; e < s1; e++) {
        int   s = g_srcv[e];
        float w = g_wv[e];
        float2 hv = h2[(size_t)s * 32 + lane];
        acc.x = fmaf(hv.x, w, acc.x);
        acc.y = fmaf(hv.y, w, acc.y);
    }
    float2 bv = ((const float2*)b)[lane];
    acc.x += bv.x;
    acc.y += bv.y;
    ((float2*)out)[(size_t)gw * 32 + lane] = acc;
}

extern "C" void kernel_launch(void* const* d_in, const int* in_sizes, int n_in,
                              void* d_out, int out_size) {
    const float* x  = (const float*)d_in[0];
    const void*  ei = d_in[1];
    const float* W1 = (const float*)d_in[2];
    const float* b1 = (const float*)d_in[3];
    const float* W2 = (const float*)d_in[4];
    const float* b2 = (const float*)d_in[5];
    float* out = (float*)d_out;

    float *ph, *pa, *ph2;
    cudaGetSymbolAddress((void**)&ph,  g_h);
    cudaGetSymbolAddress((void**)&pa,  g_a);
    cudaGetSymbolAddress((void**)&ph2, g_h2);

    const int TB = 256;
    k_detect<<<1, 256>>>((const int*)ei);
    k_zero_deg<<<(NN + TB - 1) / TB, TB>>>();
    k_count<<<(EE + TB - 1) / TB, TB>>>(ei);
    k_dinv<<<(NN + TB - 1) / TB, TB>>>();
    k_scan<<<1, 1024>>>();
    k_build<<<(EE + TB - 1) / TB, TB>>>(ei);

    // conv1: h = x @ W1 ; a = relu(agg(h) + b1)
    k_gemm<HIDC><<<dim3((NN + 63) / 64, HIDC / 64), 256>>>(x, W1, ph);
    k_agg1<<<((NN * 32) + TB - 1) / TB, TB>>>(b1);

    // conv2: h2 = a @ W2 ; out = agg(h2) + b2
    k_gemm<OC><<<dim3((NN + 63) / 64, OC / 64), 256>>>(pa, W2, ph2);
    k_agg2<<<((NN * 32) + TB - 1) / TB, TB>>>(b2, out);
}

// round 5
// speedup vs baseline: 1.0065x; 1.0065x over previous
#include <cuda_runtime.h>
#include <math.h>

#define NN 100000
#define EE 1600000
#define KC 128      // IN_C and HID (both 128)
#define HIDC 128
#define OC 64

// ---- device scratch (no allocations allowed) ----
__device__ int   g_deg[NN];
__device__ float g_dinv[NN];
__device__ int   g_colptr[NN + 1];
__device__ int   g_fill[NN];
__device__ int   g_srcv[EE];
__device__ float g_wv[EE];
__device__ float g_h [(size_t)NN * HIDC];  // x @ W1
__device__ float g_a [(size_t)NN * HIDC];  // relu(agg1 + b1)
__device__ float g_h2[(size_t)NN * OC];    // g_a @ W2
__device__ int   g_is64;

// ---- dtype detection: int64 edge_index has zero high words (values < 2^31) ----
__global__ void k_detect(const int* __restrict__ ei32) {
    __shared__ int nz;
    if (threadIdx.x == 0) nz = 0;
    __syncthreads();
    for (int i = threadIdx.x; i < 4096; i += blockDim.x) {
        if (ei32[2 * i + 1] != 0) nz = 1;  // benign race
    }
    __syncthreads();
    if (threadIdx.x == 0) g_is64 = nz ? 0 : 1;
}

__device__ __forceinline__ int edge_at(const void* ei, size_t idx, int is64) {
    if (is64) return (int)((const long long*)ei)[idx];
    return ((const int*)ei)[idx];
}

__global__ void k_zero_deg() {
    int i = blockIdx.x * blockDim.x + threadIdx.x;
    if (i < NN) g_deg[i] = 0;
}

__global__ void k_count(const void* __restrict__ ei) {
    int e = blockIdx.x * blockDim.x + threadIdx.x;
    if (e >= EE) return;
    int is64 = g_is64;
    int c = edge_at(ei, (size_t)EE + e, is64);
    atomicAdd(&g_deg[c], 1);
}

__global__ void k_dinv() {
    int i = blockIdx.x * blockDim.x + threadIdx.x;
    if (i < NN) {
        int d = g_deg[i];
        g_dinv[i] = (d > 0) ? 1.0f / sqrtf((float)d) : 0.0f;
    }
}

// single-block exclusive scan of g_deg -> g_colptr / g_fill
__global__ void k_scan() {
    __shared__ int sh[1024];
    const int T = 1024;
    const int CH = (NN + T - 1) / T;  // 98
    int t = threadIdx.x;
    int lo = t * CH;
    int hi = min(lo + CH, NN);
    int s = 0;
    for (int i = lo; i < hi; i++) s += g_deg[i];
    sh[t] = s;
    __syncthreads();
    for (int off = 1; off < T; off <<= 1) {
        int v = 0;
        if (t >= off) v = sh[t - off];
        __syncthreads();
        if (t >= off) sh[t] += v;
        __syncthreads();
    }
    int run = sh[t] - s;  // exclusive prefix
    for (int i = lo; i < hi; i++) {
        g_colptr[i] = run;
        g_fill[i]   = run;
        run += g_deg[i];
    }
    if (t == T - 1) g_colptr[NN] = sh[T - 1];
}

__global__ void k_build(const void* __restrict__ ei) {
    int e = blockIdx.x * blockDim.x + threadIdx.x;
    if (e >= EE) return;
    int is64 = g_is64;
    int r = edge_at(ei, (size_t)e, is64);
    int c = edge_at(ei, (size_t)EE + e, is64);
    float w = g_dinv[r] * g_dinv[c];
    int pos = atomicAdd(&g_fill[c], 1);
    g_srcv[pos] = r;
    g_wv[pos]   = w;
}

// ---- SGEMM: Y[NN,OUTC] = X[NN,128] @ W[128,OUTC], 64x64 tile, 4x4/thread ----
template <int OUTC>
__global__ __launch_bounds__(256) void k_gemm(const float* __restrict__ X,
                                              const float* __restrict__ W,
                                              float* __restrict__ Y) {
    __shared__ float xs[64 * 64];  // xs[kk*64 + r]
    __shared__ float ws[64 * 64];  // ws[kk*64 + c]
    int row0 = blockIdx.x * 64;
    int col0 = blockIdx.y * 64;
    int tid  = threadIdx.x;
    int tr = (tid >> 4) << 2;   // 0..60
    int tc = (tid & 15) << 2;   // 0..60
    float acc[4][4] = {};

    for (int kb = 0; kb < KC; kb += 64) {
        // load W chunk: consecutive tid -> consecutive c (coalesced)
        for (int i = tid; i < 4096; i += 256) {
            int c = i & 63, kk = i >> 6;
            ws[kk * 64 + c] = W[(size_t)(kb + kk) * OUTC + col0 + c];
        }
        // load X chunk transposed: consecutive tid -> consecutive kk (coalesced)
        for (int i = tid; i < 4096; i += 256) {
            int kk = i & 63, r = i >> 6;
            int gr = row0 + r;
            xs[kk * 64 + r] = (gr < NN) ? X[(size_t)gr * KC + kb + kk] : 0.0f;
        }
        __syncthreads();
#pragma unroll 16
        for (int kk = 0; kk < 64; kk++) {
            float4 xv = *(const float4*)&xs[kk * 64 + tr];
            float4 wv = *(const float4*)&ws[kk * 64 + tc];
            acc[0][0] = fmaf(xv.x, wv.x, acc[0][0]);
            acc[0][1] = fmaf(xv.x, wv.y, acc[0][1]);
            acc[0][2] = fmaf(xv.x, wv.z, acc[0][2]);
            acc[0][3] = fmaf(xv.x, wv.w, acc[0][3]);
            acc[1][0] = fmaf(xv.y, wv.x, acc[1][0]);
            acc[1][1] = fmaf(xv.y, wv.y, acc[1][1]);
            acc[1][2] = fmaf(xv.y, wv.z, acc[1][2]);
            acc[1][3] = fmaf(xv.y, wv.w, acc[1][3]);
            acc[2][0] = fmaf(xv.z, wv.x, acc[2][0]);
            acc[2][1] = fmaf(xv.z, wv.y, acc[2][1]);
            acc[2][2] = fmaf(xv.z, wv.z, acc[2][2]);
            acc[2][3] = fmaf(xv.z, wv.w, acc[2][3]);
            acc[3][0] = fmaf(xv.w, wv.x, acc[3][0]);
            acc[3][1] = fmaf(xv.w, wv.y, acc[3][1]);
            acc[3][2] = fmaf(xv.w, wv.z, acc[3][2]);
            acc[3][3] = fmaf(xv.w, wv.w, acc[3][3]);
        }
        __syncthreads();
    }
    for (int i = 0; i < 4; i++) {
        int gr = row0 + tr + i;
        if (gr < NN) {
            float4 o = make_float4(acc[i][0], acc[i][1], acc[i][2], acc[i][3]);
            *(float4*)&Y[(size_t)gr * OUTC + col0 + tc] = o;
        }
    }
}

// ---- aggregation conv1: warp per node, 128 channels (float4/lane), +b1, relu ----
__global__ __launch_bounds__(256) void k_agg1(const float* __restrict__ b) {
    int gw   = (blockIdx.x * blockDim.x + threadIdx.x) >> 5;
    int lane = threadIdx.x & 31;
    if (gw >= NN) return;
    int s0 = g_colptr[gw], s1 = g_colptr[gw + 1];
    const float4* h4 = (const float4*)g_h;
    float4 acc = make_float4(0.f, 0.f, 0.f, 0.f);
    for (int e = s0; e < s1; e++) {
        int   s = g_srcv[e];   // uniform across warp (broadcast)
        float w = g_wv[e];
        float4 hv = h4[(size_t)s * 32 + lane];
        acc.x = fmaf(hv.x, w, acc.x);
        acc.y = fmaf(hv.y, w, acc.y);
        acc.z = fmaf(hv.z, w, acc.z);
        acc.w = fmaf(hv.w, w, acc.w);
    }
    float4 bv = ((const float4*)b)[lane];
    acc.x = fmaxf(acc.x + bv.x, 0.f);
    acc.y = fmaxf(acc.y + bv.y, 0.f);
    acc.z = fmaxf(acc.z + bv.z, 0.f);
    acc.w = fmaxf(acc.w + bv.w, 0.f);
    ((float4*)g_a)[(size_t)gw * 32 + lane] = acc;
}

// ---- aggregation conv2: warp per node, 64 channels (float2/lane), +b2 ----
__global__ __launch_bounds__(256) void k_agg2(const float* __restrict__ b,
                                              float* __restrict__ out) {
    int gw   = (blockIdx.x * blockDim.x + threadIdx.x) >> 5;
    int lane = threadIdx.x & 31;
    if (gw >= NN) return;
    int s0 = g_colptr[gw], s1 = g_colptr[gw + 1];
    const float2* h2 = (const float2*)g_h2;
    float2 acc = make_float2(0.f, 0.f);
    for (int e = s0; e < s1; e++) {
        int   s = g_srcv[e];
        float w = g_wv[e];
        float2 hv = h2[(size_t)s * 32 + lane];
        acc.x = fmaf(hv.x, w, acc.x);
        acc.y = fmaf(hv.y, w, acc.y);
    }
    float2 bv = ((const float2*)b)[lane];
    acc.x += bv.x;
    acc.y += bv.y;
    ((float2*)out)[(size_t)gw * 32 + lane] = acc;
}

extern "C" void kernel_launch(void* const* d_in, const int* in_sizes, int n_in,
                              void* d_out, int out_size) {
    const float* x  = (const float*)d_in[0];
    const void*  ei = d_in[1];
    const float* W1 = (const float*)d_in[2];
    const float* b1 = (const float*)d_in[3];
    const float* W2 = (const float*)d_in[4];
    const float* b2 = (const float*)d_in[5];
    float* out = (float*)d_out;

    float *ph, *pa, *ph2;
    cudaGetSymbolAddress((void**)&ph,  g_h);
    cudaGetSymbolAddress((void**)&pa,  g_a);
    cudaGetSymbolAddress((void**)&ph2, g_h2);

    const int TB = 256;
    k_detect<<<1, 256>>>((const int*)ei);
    k_zero_deg<<<(NN + TB - 1) / TB, TB>>>();
    k_count<<<(EE + TB - 1) / TB, TB>>>(ei);
    k_dinv<<<(NN + TB - 1) / TB, TB>>>();
    k_scan<<<1, 1024>>>();
    k_build<<<(EE + TB - 1) / TB, TB>>>(ei);

    // conv1: h = x @ W1 ; a = relu(agg(h) + b1)
    k_gemm<HIDC><<<dim3((NN + 63) / 64, HIDC / 64), 256>>>(x, W1, ph);
    k_agg1<<<((NN * 32) + TB - 1) / TB, TB>>>(b1);

    // conv2: h2 = a @ W2 ; out = agg(h2) + b2
    k_gemm<OC><<<dim3((NN + 63) / 64, OC / 64), 256>>>(pa, W2, ph2);
    k_agg2<<<((NN * 32) + TB - 1) / TB, TB>>>(b2, out);
}

// round 6
// speedup vs baseline: 1.1344x; 1.1270x over previous
#include <cuda_runtime.h>
#include <math.h>

#define NN 100000
#define EE 1600000
#define KC 128      // IN_C and HID (both 128)
#define HIDC 128
#define OC 64

#define GB1 ((NN + 127) / 128)   // 782 gemm1 blocks
#define CB  146                  // count blocks in fat kernel

// ---- device scratch (no allocations allowed) ----
__device__ int   g_deg[NN];
__device__ float g_dinv[NN];
__device__ int   g_colptr[NN + 1];
__device__ int   g_fill[NN];
__device__ int2  g_ew[EE];                 // (src, weight bits) interleaved
__device__ float g_h [(size_t)NN * HIDC];  // x @ W1
__device__ float g_a [(size_t)NN * HIDC];  // relu(agg1 + b1)
__device__ float g_h2[(size_t)NN * OC];    // g_a @ W2
__device__ int   g_is64;

__device__ __forceinline__ int edge_at(const void* ei, size_t idx, int is64) {
    if (is64) return (int)((const long long*)ei)[idx];
    return ((const int*)ei)[idx];
}

// ---- init: zero degrees + dtype detect (block 0) ----
__global__ void k_init(const int* __restrict__ ei32) {
    int i = blockIdx.x * blockDim.x + threadIdx.x;
    if (i < NN) g_deg[i] = 0;
    if (blockIdx.x == 0) {
        __shared__ int nz;
        if (threadIdx.x == 0) nz = 0;
        __syncthreads();
        for (int j = threadIdx.x; j < 4096; j += blockDim.x) {
            if (ei32[2 * j + 1] != 0) nz = 1;  // benign race
        }
        __syncthreads();
        if (threadIdx.x == 0) g_is64 = nz ? 0 : 1;
    }
}

// ---- register-blocked GEMM tile: Y[128 rows x OUTC] = X[128,128] @ W[128,OUTC]
// 256 threads, 8x(OUTC==128?8:4) per thread, K chunks of 8.
template <int OUTC>
__device__ __forceinline__ void gemm_block(const float* __restrict__ X,
                                           const float* __restrict__ W,
                                           float* __restrict__ Y, int bx) {
    constexpr int TN = (OUTC == 128) ? 8 : 4;
    __shared__ float xs[8 * 132];       // xs[kk*132 + r], padded stride kills STS conflicts
    __shared__ float ws[8 * OUTC];      // ws[kk*OUTC + c]
    int tid  = threadIdx.x;
    int row0 = bx * 128;
    int tx = tid & 15, ty = tid >> 4;
    int tr = ty * 8,   tc = tx * TN;
    float acc[8][TN];
#pragma unroll
    for (int i = 0; i < 8; i++)
#pragma unroll
        for (int j = 0; j < TN; j++) acc[i][j] = 0.0f;

    int lr = tid >> 1;            // 0..127 (row to load)
    int lk = (tid & 1) * 4;       // 0 or 4 (k sub-offset)

    for (int kb = 0; kb < KC; kb += 8) {
        // X chunk: one float4 per thread, store transposed
        float4 xv = make_float4(0.f, 0.f, 0.f, 0.f);
        int gr = row0 + lr;
        if (gr < NN) xv = *(const float4*)&X[(size_t)gr * KC + kb + lk];
        xs[(lk + 0) * 132 + lr] = xv.x;
        xs[(lk + 1) * 132 + lr] = xv.y;
        xs[(lk + 2) * 132 + lr] = xv.z;
        xs[(lk + 3) * 132 + lr] = xv.w;
        // W chunk
        if (OUTC == 128) {
            int wk = tid >> 5, wc = (tid & 31) * 4;
            *(float4*)&ws[wk * OUTC + wc] = *(const float4*)&W[(size_t)(kb + wk) * OUTC + wc];
        } else {
            int wk = tid >> 5, wc = (tid & 31) * 2;
            *(float2*)&ws[wk * OUTC + wc] = *(const float2*)&W[(size_t)(kb + wk) * OUTC + wc];
        }
        __syncthreads();
#pragma unroll
        for (int kk = 0; kk < 8; kk++) {
            float xr[8];
            *(float4*)&xr[0] = *(const float4*)&xs[kk * 132 + tr];
            *(float4*)&xr[4] = *(const float4*)&xs[kk * 132 + tr + 4];
            float wr[TN];
#pragma unroll
            for (int j = 0; j < TN; j += 4)
                *(float4*)&wr[j] = *(const float4*)&ws[kk * OUTC + tc + j];
#pragma unroll
            for (int i = 0; i < 8; i++)
#pragma unroll
                for (int j = 0; j < TN; j++)
                    acc[i][j] = fmaf(xr[i], wr[j], acc[i][j]);
        }
        __syncthreads();
    }
#pragma unroll
    for (int i = 0; i < 8; i++) {
        int gr = row0 + tr + i;
        if (gr < NN) {
#pragma unroll
            for (int j = 0; j < TN; j += 4) {
                float4 o = make_float4(acc[i][j], acc[i][j+1], acc[i][j+2], acc[i][j+3]);
                *(float4*)&Y[(size_t)gr * OUTC + tc + j] = o;
            }
        }
    }
}

// ---- fat kernel: blocks [0,CB) count degrees, blocks [CB, CB+GB1) do GEMM1 ----
__global__ __launch_bounds__(256) void k_fat1(const float* __restrict__ X,
                                              const float* __restrict__ W1,
                                              const void* __restrict__ ei) {
    if (blockIdx.x < CB) {
        int is64 = g_is64;
        int t = blockIdx.x * 256 + threadIdx.x;
        for (int e = t; e < EE; e += CB * 256) {
            int c = edge_at(ei, (size_t)EE + e, is64);
            atomicAdd(&g_deg[c], 1);
        }
    } else {
        gemm_block<HIDC>(X, W1, g_h, blockIdx.x - CB);
    }
}

// ---- single-block exclusive scan of g_deg (+ fused dinv) ----
__global__ void k_scan() {
    __shared__ int sh[1024];
    const int T = 1024;
    const int CH = (NN + T - 1) / T;  // 98
    int t = threadIdx.x;
    int lo = t * CH;
    int hi = min(lo + CH, NN);
    int s = 0;
    for (int i = lo; i < hi; i++) {
        int d = g_deg[i];
        s += d;
        g_dinv[i] = (d > 0) ? rsqrtf((float)d) : 0.0f;
    }
    sh[t] = s;
    __syncthreads();
    for (int off = 1; off < T; off <<= 1) {
        int v = 0;
        if (t >= off) v = sh[t - off];
        __syncthreads();
        if (t >= off) sh[t] += v;
        __syncthreads();
    }
    int run = sh[t] - s;  // exclusive prefix
    for (int i = lo; i < hi; i++) {
        g_colptr[i] = run;
        g_fill[i]   = run;
        run += g_deg[i];
    }
    if (t == T - 1) g_colptr[NN] = sh[T - 1];
}

__global__ void k_build(const void* __restrict__ ei) {
    int e = blockIdx.x * blockDim.x + threadIdx.x;
    if (e >= EE) return;
    int is64 = g_is64;
    int r = edge_at(ei, (size_t)e, is64);
    int c = edge_at(ei, (size_t)EE + e, is64);
    float w = g_dinv[r] * g_dinv[c];
    int pos = atomicAdd(&g_fill[c], 1);
    g_ew[pos] = make_int2(r, __float_as_int(w));
}

// ---- aggregation conv1: warp per node, 128 ch (float4/lane), +b1, relu, x4 unroll
__global__ __launch_bounds__(256) void k_agg1(const float* __restrict__ b) {
    int gw   = (blockIdx.x * blockDim.x + threadIdx.x) >> 5;
    int lane = threadIdx.x & 31;
    if (gw >= NN) return;
    int e  = g_colptr[gw];
    int s1 = g_colptr[gw + 1];
    const float4* h4 = (const float4*)g_h;
    float4 acc = make_float4(0.f, 0.f, 0.f, 0.f);
    for (; e + 4 <= s1; e += 4) {
        int2 e0 = g_ew[e], e1 = g_ew[e + 1], e2 = g_ew[e + 2], e3 = g_ew[e + 3];
        float4 v0 = h4[(size_t)e0.x * 32 + lane];
        float4 v1 = h4[(size_t)e1.x * 32 + lane];
        float4 v2 = h4[(size_t)e2.x * 32 + lane];
        float4 v3 = h4[(size_t)e3.x * 32 + lane];
        float w0 = __int_as_float(e0.y), w1 = __int_as_float(e1.y);
        float w2 = __int_as_float(e2.y), w3 = __int_as_float(e3.y);
        acc.x = fmaf(v0.x, w0, acc.x); acc.y = fmaf(v0.y, w0, acc.y);
        acc.z = fmaf(v0.z, w0, acc.z); acc.w = fmaf(v0.w, w0, acc.w);
        acc.x = fmaf(v1.x, w1, acc.x); acc.y = fmaf(v1.y, w1, acc.y);
        acc.z = fmaf(v1.z, w1, acc.z); acc.w = fmaf(v1.w, w1, acc.w);
        acc.x = fmaf(v2.x, w2, acc.x); acc.y = fmaf(v2.y, w2, acc.y);
        acc.z = fmaf(v2.z, w2, acc.z); acc.w = fmaf(v2.w, w2, acc.w);
        acc.x = fmaf(v3.x, w3, acc.x); acc.y = fmaf(v3.y, w3, acc.y);
        acc.z = fmaf(v3.z, w3, acc.z); acc.w = fmaf(v3.w, w3, acc.w);
    }
    for (; e < s1; e++) {
        int2 ew = g_ew[e];
        float w = __int_as_float(ew.y);
        float4 hv = h4[(size_t)ew.x * 32 + lane];
        acc.x = fmaf(hv.x, w, acc.x); acc.y = fmaf(hv.y, w, acc.y);
        acc.z = fmaf(hv.z, w, acc.z); acc.w = fmaf(hv.w, w, acc.w);
    }
    float4 bv = ((const float4*)b)[lane];
    acc.x = fmaxf(acc.x + bv.x, 0.f);
    acc.y = fmaxf(acc.y + bv.y, 0.f);
    acc.z = fmaxf(acc.z + bv.z, 0.f);
    acc.w = fmaxf(acc.w + bv.w, 0.f);
    ((float4*)g_a)[(size_t)gw * 32 + lane] = acc;
}

// ---- GEMM2 standalone ----
__global__ __launch_bounds__(256) void k_gemm2(const float* __restrict__ W2) {
    gemm_block<OC>(g_a, W2, g_h2, blockIdx.x);
}

// ---- aggregation conv2: warp per node, 64 ch (float2/lane), +b2, x4 unroll ----
__global__ __launch_bounds__(256) void k_agg2(const float* __restrict__ b,
                                              float* __restrict__ out) {
    int gw   = (blockIdx.x * blockDim.x + threadIdx.x) >> 5;
    int lane = threadIdx.x & 31;
    if (gw >= NN) return;
    int e  = g_colptr[gw];
    int s1 = g_colptr[gw + 1];
    const float2* h2 = (const float2*)g_h2;
    float2 acc = make_float2(0.f, 0.f);
    for (; e + 4 <= s1; e += 4) {
        int2 e0 = g_ew[e], e1 = g_ew[e + 1], e2 = g_ew[e + 2], e3 = g_ew[e + 3];
        float2 v0 = h2[(size_t)e0.x * 32 + lane];
        float2 v1 = h2[(size_t)e1.x * 32 + lane];
        float2 v2 = h2[(size_t)e2.x * 32 + lane];
        float2 v3 = h2[(size_t)e3.x * 32 + lane];
        float w0 = __int_as_float(e0.y), w1 = __int_as_float(e1.y);
        float w2 = __int_as_float(e2.y), w3 = __int_as_float(e3.y);
        acc.x = fmaf(v0.x, w0, acc.x); acc.y = fmaf(v0.y, w0, acc.y);
        acc.x = fmaf(v1.x, w1, acc.x); acc.y = fmaf(v1.y, w1, acc.y);
        acc.x = fmaf(v2.x, w2, acc.x); acc.y = fmaf(v2.y, w2, acc.y);
        acc.x = fmaf(v3.x, w3, acc.x); acc.y = fmaf(v3.y, w3, acc.y);
    }
    for (; e < s1; e++) {
        int2 ew = g_ew[e];
        float w = __int_as_float(ew.y);
        float2 hv = h2[(size_t)ew.x * 32 + lane];
        acc.x = fmaf(hv.x, w, acc.x); acc.y = fmaf(hv.y, w, acc.y);
    }
    float2 bv = ((const float2*)b)[lane];
    acc.x += bv.x;
    acc.y += bv.y;
    ((float2*)out)[(size_t)gw * 32 + lane] = acc;
}

extern "C" void kernel_launch(void* const* d_in, const int* in_sizes, int n_in,
                              void* d_out, int out_size) {
    const float* x  = (const float*)d_in[0];
    const void*  ei = d_in[1];
    const float* W1 = (const float*)d_in[2];
    const float* b1 = (const float*)d_in[3];
    const float* W2 = (const float*)d_in[4];
    const float* b2 = (const float*)d_in[5];
    float* out = (float*)d_out;

    const int TB = 256;
    k_init<<<(NN + TB - 1) / TB, TB>>>((const int*)ei);
    k_fat1<<<CB + GB1, TB>>>(x, W1, ei);             // degree count ∥ GEMM1
    k_scan<<<1, 1024>>>();                           // prefix scan + dinv
    k_build<<<(EE + TB - 1) / TB, TB>>>(ei);         // CSR fill with weights
    k_agg1<<<(NN * 32 + TB - 1) / TB, TB>>>(b1);     // S·h + b1, relu
    k_gemm2<<<GB1, TB>>>(W2);                        // a @ W2
    k_agg2<<<(NN * 32 + TB - 1) / TB, TB>>>(b2, out);// S·h2 + b2
}

// round 7
// speedup vs baseline: 1.8490x; 1.6300x over previous
#include <cuda_runtime.h>
#include <math.h>

#define NN 100000
#define EE 1600000
#define KC 128      // IN_C and HID (both 128)
#define HIDC 128
#define OC 64

#define GB1 ((NN + 127) / 128)   // 782 gemm tile blocks
#define CB  146                  // count blocks in fat kernel
#define SB  ((NN + 1023) / 1024) // 98 scan blocks

// ---- device scratch (no allocations allowed) ----
__device__ int   g_deg[NN];
__device__ float g_dinv[NN];
__device__ int   g_colptr[NN + 1];
__device__ int   g_rank[EE];               // within-bucket rank per edge
__device__ int   g_btot[SB];
__device__ int   g_boff[SB];
__device__ int2  g_ew[EE];                 // (src, weight bits) interleaved
__device__ float g_h [(size_t)NN * HIDC];  // x @ W1
__device__ float g_a [(size_t)NN * HIDC];  // relu(agg1 + b1)
__device__ float g_h2[(size_t)NN * OC];    // g_a @ W2
__device__ int   g_is64;

__device__ __forceinline__ int edge_at(const void* ei, size_t idx, int is64) {
    if (is64) return (int)((const long long*)ei)[idx];
    return ((const int*)ei)[idx];
}

// ---- init: zero degrees + dtype detect (block 0) ----
__global__ void k_init(const int* __restrict__ ei32) {
    int i = blockIdx.x * blockDim.x + threadIdx.x;
    if (i < NN) g_deg[i] = 0;
    if (blockIdx.x == 0) {
        __shared__ int nz;
        if (threadIdx.x == 0) nz = 0;
        __syncthreads();
        for (int j = threadIdx.x; j < 4096; j += blockDim.x) {
            if (ei32[2 * j + 1] != 0) nz = 1;  // benign race
        }
        __syncthreads();
        if (threadIdx.x == 0) g_is64 = nz ? 0 : 1;
    }
}

// ---- double-buffered register-blocked GEMM tile:
// Y[128 x OUTC] = X[128,128] @ W[128,OUTC]; 256 threads, 8x(8|4)/thread.
template <int OUTC>
__device__ __forceinline__ void gemm_block(const float* __restrict__ X,
                                           const float* __restrict__ W,
                                           float* __restrict__ Y, int bx) {
    constexpr int TN = (OUTC == 128) ? 8 : 4;
    __shared__ float xs[2][8 * 132];   // [kk*132 + r], padded
    __shared__ float ws[2][8 * OUTC];  // [kk*OUTC + c]
    const int tid  = threadIdx.x;
    const int row0 = bx * 128;
    const int tx = tid & 15, ty = tid >> 4;
    const int tr = ty * 8,   tc = tx * TN;
    const int lr = tid >> 1, lk = (tid & 1) * 4;
    const int wk = tid >> 5;
    const int wc4 = (tid & 31) * 4, wc2 = (tid & 31) * 2;
    const int gr = row0 + lr;

    float acc[8][TN];
#pragma unroll
    for (int i = 0; i < 8; i++)
#pragma unroll
        for (int j = 0; j < TN; j++) acc[i][j] = 0.0f;

    // prologue: load chunk 0 into buffer 0
    float4 xv = make_float4(0.f, 0.f, 0.f, 0.f);
    if (gr < NN) xv = __ldcs((const float4*)&X[(size_t)gr * KC + lk]);
    float4 wv4; float2 wv2;
    if (OUTC == 128) wv4 = *(const float4*)&W[(size_t)wk * OUTC + wc4];
    else             wv2 = *(const float2*)&W[(size_t)wk * OUTC + wc2];
    xs[0][(lk + 0) * 132 + lr] = xv.x;
    xs[0][(lk + 1) * 132 + lr] = xv.y;
    xs[0][(lk + 2) * 132 + lr] = xv.z;
    xs[0][(lk + 3) * 132 + lr] = xv.w;
    if (OUTC == 128) *(float4*)&ws[0][wk * OUTC + wc4] = wv4;
    else             *(float2*)&ws[0][wk * OUTC + wc2] = wv2;
    __syncthreads();

    int buf = 0;
    for (int kb = 0; kb < KC; kb += 8) {
        const bool more = (kb + 8) < KC;
        if (more) {
            xv = make_float4(0.f, 0.f, 0.f, 0.f);
            if (gr < NN) xv = __ldcs((const float4*)&X[(size_t)gr * KC + kb + 8 + lk]);
            if (OUTC == 128) wv4 = *(const float4*)&W[(size_t)(kb + 8 + wk) * OUTC + wc4];
            else             wv2 = *(const float2*)&W[(size_t)(kb + 8 + wk) * OUTC + wc2];
        }
#pragma unroll
        for (int kk = 0; kk < 8; kk++) {
            float xr[8];
            *(float4*)&xr[0] = *(const float4*)&xs[buf][kk * 132 + tr];
            *(float4*)&xr[4] = *(const float4*)&xs[buf][kk * 132 + tr + 4];
            float wr[TN];
#pragma unroll
            for (int j = 0; j < TN; j += 4)
                *(float4*)&wr[j] = *(const float4*)&ws[buf][kk * OUTC + tc + j];
#pragma unroll
            for (int i = 0; i < 8; i++)
#pragma unroll
                for (int j = 0; j < TN; j++)
                    acc[i][j] = fmaf(xr[i], wr[j], acc[i][j]);
        }
        if (more) {
            int nb = buf ^ 1;
            xs[nb][(lk + 0) * 132 + lr] = xv.x;
            xs[nb][(lk + 1) * 132 + lr] = xv.y;
            xs[nb][(lk + 2) * 132 + lr] = xv.z;
            xs[nb][(lk + 3) * 132 + lr] = xv.w;
            if (OUTC == 128) *(float4*)&ws[nb][wk * OUTC + wc4] = wv4;
            else             *(float2*)&ws[nb][wk * OUTC + wc2] = wv2;
        }
        __syncthreads();
        buf ^= 1;
    }
#pragma unroll
    for (int i = 0; i < 8; i++) {
        int orow = row0 + tr + i;
        if (orow < NN) {
#pragma unroll
            for (int j = 0; j < TN; j += 4) {
                float4 o = make_float4(acc[i][j], acc[i][j+1], acc[i][j+2], acc[i][j+3]);
                *(float4*)&Y[(size_t)orow * OUTC + tc + j] = o;
            }
        }
    }
}

// ---- fat kernel: blocks [0,CB) count degrees + record ranks; rest do GEMM1 ----
__global__ __launch_bounds__(256) void k_fat1(const float* __restrict__ X,
                                              const float* __restrict__ W1,
                                              const void* __restrict__ ei) {
    if (blockIdx.x < CB) {
        int is64 = g_is64;
        int t = blockIdx.x * 256 + threadIdx.x;
        for (int e = t; e < EE; e += CB * 256) {
            int c = edge_at(ei, (size_t)EE + e, is64);
            g_rank[e] = atomicAdd(&g_deg[c], 1);
        }
    } else {
        gemm_block<HIDC>(X, W1, g_h, blockIdx.x - CB);
    }
}

// ---- 3-phase exclusive scan of g_deg (+ fused dinv) ----
__global__ __launch_bounds__(1024) void k_scanA() {
    __shared__ int sh[1024];
    int t = threadIdx.x;
    int i = blockIdx.x * 1024 + t;
    int d = 0;
    if (i < NN) {
        d = g_deg[i];
        g_dinv[i] = (d > 0) ? rsqrtf((float)d) : 0.0f;
    }
    sh[t] = d;
    __syncthreads();
    for (int off = 1; off < 1024; off <<= 1) {
        int v = 0;
        if (t >= off) v = sh[t - off];
        __syncthreads();
        if (t >= off) sh[t] += v;
        __syncthreads();
    }
    if (i < NN) g_colptr[i] = sh[t] - d;   // local exclusive prefix
    if (t == 1023) g_btot[blockIdx.x] = sh[1023];
}

__global__ __launch_bounds__(128) void k_scanB() {
    __shared__ int sh[128];
    int t = threadIdx.x;
    int v = (t < SB) ? g_btot[t] : 0;
    sh[t] = v;
    __syncthreads();
    for (int off = 1; off < 128; off <<= 1) {
        int u = 0;
        if (t >= off) u = sh[t - off];
        __syncthreads();
        if (t >= off) sh[t] += u;
        __syncthreads();
    }
    if (t < SB) g_boff[t] = sh[t] - v;
    if (t == 127) g_colptr[NN] = sh[127];
}

__global__ __launch_bounds__(1024) void k_scanC() {
    int i = blockIdx.x * 1024 + threadIdx.x;
    if (i < NN) g_colptr[i] += g_boff[blockIdx.x];
}

// ---- CSR fill: atomic-free (pos = colptr[c] + rank[e]) ----
__global__ __launch_bounds__(256) void k_build(const void* __restrict__ ei) {
    int e = blockIdx.x * blockDim.x + threadIdx.x;
    if (e >= EE) return;
    int is64 = g_is64;
    int r = edge_at(ei, (size_t)e, is64);
    int c = edge_at(ei, (size_t)EE + e, is64);
    float w = g_dinv[r] * g_dinv[c];
    int pos = g_colptr[c] + g_rank[e];
    g_ew[pos] = make_int2(r, __float_as_int(w));
}

// ---- aggregation conv1: warp per node, 128 ch (float4/lane), +b1, relu ----
__global__ __launch_bounds__(256) void k_agg1(const float* __restrict__ b) {
    int gw   = (blockIdx.x * blockDim.x + threadIdx.x) >> 5;
    int lane = threadIdx.x & 31;
    if (gw >= NN) return;
    int e  = g_colptr[gw];
    int s1 = g_colptr[gw + 1];
    const float4* h4 = (const float4*)g_h;
    float4 acc = make_float4(0.f, 0.f, 0.f, 0.f);
    for (; e + 4 <= s1; e += 4) {
        int2 e0 = __ldcs(&g_ew[e]);
        int2 e1 = __ldcs(&g_ew[e + 1]);
        int2 e2 = __ldcs(&g_ew[e + 2]);
        int2 e3 = __ldcs(&g_ew[e + 3]);
        float4 v0 = __ldg(&h4[(size_t)e0.x * 32 + lane]);
        float4 v1 = __ldg(&h4[(size_t)e1.x * 32 + lane]);
        float4 v2 = __ldg(&h4[(size_t)e2.x * 32 + lane]);
        float4 v3 = __ldg(&h4[(size_t)e3.x * 32 + lane]);
        float w0 = __int_as_float(e0.y), w1 = __int_as_float(e1.y);
        float w2 = __int_as_float(e2.y), w3 = __int_as_float(e3.y);
        acc.x = fmaf(v0.x, w0, acc.x); acc.y = fmaf(v0.y, w0, acc.y);
        acc.z = fmaf(v0.z, w0, acc.z); acc.w = fmaf(v0.w, w0, acc.w);
        acc.x = fmaf(v1.x, w1, acc.x); acc.y = fmaf(v1.y, w1, acc.y);
        acc.z = fmaf(v1.z, w1, acc.z); acc.w = fmaf(v1.w, w1, acc.w);
        acc.x = fmaf(v2.x, w2, acc.x); acc.y = fmaf(v2.y, w2, acc.y);
        acc.z = fmaf(v2.z, w2, acc.z); acc.w = fmaf(v2.w, w2, acc.w);
        acc.x = fmaf(v3.x, w3, acc.x); acc.y = fmaf(v3.y, w3, acc.y);
        acc.z = fmaf(v3.z, w3, acc.z); acc.w = fmaf(v3.w, w3, acc.w);
    }
    for (; e < s1; e++) {
        int2 ew = __ldcs(&g_ew[e]);
        float w = __int_as_float(ew.y);
        float4 hv = __ldg(&h4[(size_t)ew.x * 32 + lane]);
        acc.x = fmaf(hv.x, w, acc.x); acc.y = fmaf(hv.y, w, acc.y);
        acc.z = fmaf(hv.z, w, acc.z); acc.w = fmaf(hv.w, w, acc.w);
    }
    float4 bv = ((const float4*)b)[lane];
    acc.x = fmaxf(acc.x + bv.x, 0.f);
    acc.y = fmaxf(acc.y + bv.y, 0.f);
    acc.z = fmaxf(acc.z + bv.z, 0.f);
    acc.w = fmaxf(acc.w + bv.w, 0.f);
    ((float4*)g_a)[(size_t)gw * 32 + lane] = acc;
}

// ---- GEMM2 standalone ----
__global__ __launch_bounds__(256) void k_gemm2(const float* __restrict__ W2) {
    gemm_block<OC>(g_a, W2, g_h2, blockIdx.x);
}

// ---- aggregation conv2: warp per node, 64 ch (float2/lane), +b2 ----
__global__ __launch_bounds__(256) void k_agg2(const float* __restrict__ b,
                                              float* __restrict__ out) {
    int gw   = (blockIdx.x * blockDim.x + threadIdx.x) >> 5;
    int lane = threadIdx.x & 31;
    if (gw >= NN) return;
    int e  = g_colptr[gw];
    int s1 = g_colptr[gw + 1];
    const float2* h2 = (const float2*)g_h2;
    float2 acc = make_float2(0.f, 0.f);
    for (; e + 4 <= s1; e += 4) {
        int2 e0 = __ldcs(&g_ew[e]);
        int2 e1 = __ldcs(&g_ew[e + 1]);
        int2 e2 = __ldcs(&g_ew[e + 2]);
        int2 e3 = __ldcs(&g_ew[e + 3]);
        float2 v0 = __ldg(&h2[(size_t)e0.x * 32 + lane]);
        float2 v1 = __ldg(&h2[(size_t)e1.x * 32 + lane]);
        float2 v2 = __ldg(&h2[(size_t)e2.x * 32 + lane]);
        float2 v3 = __ldg(&h2[(size_t)e3.x * 32 + lane]);
        float w0 = __int_as_float(e0.y), w1 = __int_as_float(e1.y);
        float w2 = __int_as_float(e2.y), w3 = __int_as_float(e3.y);
        acc.x = fmaf(v0.x, w0, acc.x); acc.y = fmaf(v0.y, w0, acc.y);
        acc.x = fmaf(v1.x, w1, acc.x); acc.y = fmaf(v1.y, w1, acc.y);
        acc.x = fmaf(v2.x, w2, acc.x); acc.y = fmaf(v2.y, w2, acc.y);
        acc.x = fmaf(v3.x, w3, acc.x); acc.y = fmaf(v3.y, w3, acc.y);
    }
    for (; e < s1; e++) {
        int2 ew = __ldcs(&g_ew[e]);
        float w = __int_as_float(ew.y);
        float2 hv = __ldg(&h2[(size_t)ew.x * 32 + lane]);
        acc.x = fmaf(hv.x, w, acc.x); acc.y = fmaf(hv.y, w, acc.y);
    }
    float2 bv = ((const float2*)b)[lane];
    acc.x += bv.x;
    acc.y += bv.y;
    ((float2*)out)[(size_t)gw * 32 + lane] = acc;
}

extern "C" void kernel_launch(void* const* d_in, const int* in_sizes, int n_in,
                              void* d_out, int out_size) {
    const float* x  = (const float*)d_in[0];
    const void*  ei = d_in[1];
    const float* W1 = (const float*)d_in[2];
    const float* b1 = (const float*)d_in[3];
    const float* W2 = (const float*)d_in[4];
    const float* b2 = (const float*)d_in[5];
    float* out = (float*)d_out;

    const int TB = 256;
    k_init<<<(NN + TB - 1) / TB, TB>>>((const int*)ei);
    k_fat1<<<CB + GB1, TB>>>(x, W1, ei);             // {degree count + rank} ∥ GEMM1
    k_scanA<<<SB, 1024>>>();                         // block-local scan + dinv
    k_scanB<<<1, 128>>>();                           // scan of block totals
    k_scanC<<<SB, 1024>>>();                         // add offsets
    k_build<<<(EE + TB - 1) / TB, TB>>>(ei);         // atomic-free CSR fill
    k_agg1<<<(NN * 32 + TB - 1) / TB, TB>>>(b1);     // S·h + b1, relu
    k_gemm2<<<GB1, TB>>>(W2);                        // a @ W2
    k_agg2<<<(NN * 32 + TB - 1) / TB, TB>>>(b2, out);// S·h2 + b2
}

// round 8
// speedup vs baseline: 2.0827x; 1.1264x over previous
#include <cuda_runtime.h>
#include <cuda_fp16.h>
#include <math.h>

#define NN 100000
#define EE 1600000
#define KC 128      // IN_C and HID (both 128)
#define HIDC 128
#define OC 64

#define GB1 ((NN + 127) / 128)   // 782 gemm tile blocks total
#define GBH 391                  // tiles in fatA (rest in fatB)
#define CB  146                  // count blocks in fatA
#define BB  160                  // build blocks in fatB
#define SB  ((NN + 1023) / 1024) // 98 scan blocks

// ---- device scratch (no allocations allowed) ----
__device__ int    g_deg[NN];
__device__ float  g_dinv[NN];
__device__ int    g_colptr[NN + 1];
__device__ int    g_rank[EE];               // within-bucket rank per edge
__device__ int    g_btot[SB];
__device__ int    g_boff[SB];
__device__ int2   g_ew[EE];                 // (src, weight bits) interleaved
__device__ __half g_h16 [(size_t)NN * HIDC];  // x @ W1          (fp16)
__device__ float  g_a   [(size_t)NN * HIDC];  // relu(agg1 + b1) (fp32)
__device__ __half g_h216[(size_t)NN * OC];    // g_a @ W2        (fp16)
__device__ int    g_is64;

__device__ __forceinline__ int edge_at(const void* ei, size_t idx, int is64) {
    if (is64) return (int)((const long long*)ei)[idx];
    return ((const int*)ei)[idx];
}

// ---- init: zero degrees + dtype detect (block 0) ----
__global__ void k_init(const int* __restrict__ ei32) {
    int i = blockIdx.x * blockDim.x + threadIdx.x;
    if (i < NN) g_deg[i] = 0;
    if (blockIdx.x == 0) {
        __shared__ int nz;
        if (threadIdx.x == 0) nz = 0;
        __syncthreads();
        for (int j = threadIdx.x; j < 4096; j += blockDim.x) {
            if (ei32[2 * j + 1] != 0) nz = 1;  // benign race
        }
        __syncthreads();
        if (threadIdx.x == 0) g_is64 = nz ? 0 : 1;
    }
}

// ---- double-buffered register-blocked GEMM tile:
// Y[128 x OUTC](fp16) = X[128,128](fp32) @ W[128,OUTC]; 256 thr, 8x(8|4)/thr.
template <int OUTC>
__device__ __forceinline__ void gemm_block(const float* __restrict__ X,
                                           const float* __restrict__ W,
                                           __half* __restrict__ Y, int bx) {
    constexpr int TN = (OUTC == 128) ? 8 : 4;
    __shared__ float xs[2][8 * 132];   // [kk*132 + r], padded
    __shared__ float ws[2][8 * OUTC];  // [kk*OUTC + c]
    const int tid  = threadIdx.x;
    const int row0 = bx * 128;
    const int tx = tid & 15, ty = tid >> 4;
    const int tr = ty * 8,   tc = tx * TN;
    const int lr = tid >> 1, lk = (tid & 1) * 4;
    const int wk = tid >> 5;
    const int wc4 = (tid & 31) * 4, wc2 = (tid & 31) * 2;
    const int gr = row0 + lr;

    float acc[8][TN];
#pragma unroll
    for (int i = 0; i < 8; i++)
#pragma unroll
        for (int j = 0; j < TN; j++) acc[i][j] = 0.0f;

    // prologue: load chunk 0 into buffer 0
    float4 xv = make_float4(0.f, 0.f, 0.f, 0.f);
    if (gr < NN) xv = __ldcs((const float4*)&X[(size_t)gr * KC + lk]);
    float4 wv4; float2 wv2;
    if (OUTC == 128) wv4 = *(const float4*)&W[(size_t)wk * OUTC + wc4];
    else             wv2 = *(const float2*)&W[(size_t)wk * OUTC + wc2];
    xs[0][(lk + 0) * 132 + lr] = xv.x;
    xs[0][(lk + 1) * 132 + lr] = xv.y;
    xs[0][(lk + 2) * 132 + lr] = xv.z;
    xs[0][(lk + 3) * 132 + lr] = xv.w;
    if (OUTC == 128) *(float4*)&ws[0][wk * OUTC + wc4] = wv4;
    else             *(float2*)&ws[0][wk * OUTC + wc2] = wv2;
    __syncthreads();

    int buf = 0;
    for (int kb = 0; kb < KC; kb += 8) {
        const bool more = (kb + 8) < KC;
        if (more) {
            xv = make_float4(0.f, 0.f, 0.f, 0.f);
            if (gr < NN) xv = __ldcs((const float4*)&X[(size_t)gr * KC + kb + 8 + lk]);
            if (OUTC == 128) wv4 = *(const float4*)&W[(size_t)(kb + 8 + wk) * OUTC + wc4];
            else             wv2 = *(const float2*)&W[(size_t)(kb + 8 + wk) * OUTC + wc2];
        }
#pragma unroll
        for (int kk = 0; kk < 8; kk++) {
            float xr[8];
            *(float4*)&xr[0] = *(const float4*)&xs[buf][kk * 132 + tr];
            *(float4*)&xr[4] = *(const float4*)&xs[buf][kk * 132 + tr + 4];
            float wr[TN];
#pragma unroll
            for (int j = 0; j < TN; j += 4)
                *(float4*)&wr[j] = *(const float4*)&ws[buf][kk * OUTC + tc + j];
#pragma unroll
            for (int i = 0; i < 8; i++)
#pragma unroll
                for (int j = 0; j < TN; j++)
                    acc[i][j] = fmaf(xr[i], wr[j], acc[i][j]);
        }
        if (more) {
            int nb = buf ^ 1;
            xs[nb][(lk + 0) * 132 + lr] = xv.x;
            xs[nb][(lk + 1) * 132 + lr] = xv.y;
            xs[nb][(lk + 2) * 132 + lr] = xv.z;
            xs[nb][(lk + 3) * 132 + lr] = xv.w;
            if (OUTC == 128) *(float4*)&ws[nb][wk * OUTC + wc4] = wv4;
            else             *(float2*)&ws[nb][wk * OUTC + wc2] = wv2;
        }
        __syncthreads();
        buf ^= 1;
    }
#pragma unroll
    for (int i = 0; i < 8; i++) {
        int orow = row0 + tr + i;
        if (orow < NN) {
            __half2 hb[TN / 2];
#pragma unroll
            for (int j = 0; j < TN; j += 2)
                hb[j / 2] = __floats2half2_rn(acc[i][j], acc[i][j + 1]);
            if (OUTC == 128)
                *(uint4*)&Y[(size_t)orow * OUTC + tc] = *(uint4*)hb;
            else
                *(uint2*)&Y[(size_t)orow * OUTC + tc] = *(uint2*)hb;
        }
    }
}

// ---- fatA: blocks [0,CB) count degrees + record ranks; rest GEMM1 tiles [0,GBH)
__global__ __launch_bounds__(256) void k_fatA(const float* __restrict__ X,
                                              const float* __restrict__ W1,
                                              const void* __restrict__ ei) {
    if (blockIdx.x < CB) {
        int is64 = g_is64;
        int t = blockIdx.x * 256 + threadIdx.x;
        for (int e = t; e < EE; e += CB * 256) {
            int c = edge_at(ei, (size_t)EE + e, is64);
            g_rank[e] = atomicAdd(&g_deg[c], 1);
        }
    } else {
        gemm_block<HIDC>(X, W1, g_h16, blockIdx.x - CB);
    }
}

// ---- 3-phase exclusive scan of g_deg (+ fused dinv) ----
__global__ __launch_bounds__(1024) void k_scanA() {
    __shared__ int sh[1024];
    int t = threadIdx.x;
    int i = blockIdx.x * 1024 + t;
    int d = 0;
    if (i < NN) {
        d = g_deg[i];
        g_dinv[i] = (d > 0) ? rsqrtf((float)d) : 0.0f;
    }
    sh[t] = d;
    __syncthreads();
    for (int off = 1; off < 1024; off <<= 1) {
        int v = 0;
        if (t >= off) v = sh[t - off];
        __syncthreads();
        if (t >= off) sh[t] += v;
        __syncthreads();
    }
    if (i < NN) g_colptr[i] = sh[t] - d;   // local exclusive prefix
    if (t == 1023) g_btot[blockIdx.x] = sh[1023];
}

__global__ __launch_bounds__(128) void k_scanB() {
    __shared__ int sh[128];
    int t = threadIdx.x;
    int v = (t < SB) ? g_btot[t] : 0;
    sh[t] = v;
    __syncthreads();
    for (int off = 1; off < 128; off <<= 1) {
        int u = 0;
        if (t >= off) u = sh[t - off];
        __syncthreads();
        if (t >= off) sh[t] += u;
        __syncthreads();
    }
    if (t < SB) g_boff[t] = sh[t] - v;
    if (t == 127) g_colptr[NN] = sh[127];
}

__global__ __launch_bounds__(1024) void k_scanC() {
    int i = blockIdx.x * 1024 + threadIdx.x;
    if (i < NN) g_colptr[i] += g_boff[blockIdx.x];
}

// ---- fatB: blocks [0,BB) atomic-free CSR fill; rest GEMM1 tiles [GBH,GB1) ----
__global__ __launch_bounds__(256) void k_fatB(const float* __restrict__ X,
                                              const float* __restrict__ W1,
                                              const void* __restrict__ ei) {
    if (blockIdx.x < BB) {
        int is64 = g_is64;
        int t = blockIdx.x * 256 + threadIdx.x;
        for (int e = t; e < EE; e += BB * 256) {
            int r = edge_at(ei, (size_t)e, is64);
            int c = edge_at(ei, (size_t)EE + e, is64);
            float w = g_dinv[r] * g_dinv[c];
            int pos = g_colptr[c] + g_rank[e];
            g_ew[pos] = make_int2(r, __float_as_int(w));
        }
    } else {
        gemm_block<HIDC>(X, W1, g_h16, GBH + blockIdx.x - BB);
    }
}

__device__ __forceinline__ void fma4_h(float4& acc, uint2 u, float w) {
    float2 f0 = __half22float2(*(__half2*)&u.x);
    float2 f1 = __half22float2(*(__half2*)&u.y);
    acc.x = fmaf(f0.x, w, acc.x);
    acc.y = fmaf(f0.y, w, acc.y);
    acc.z = fmaf(f1.x, w, acc.z);
    acc.w = fmaf(f1.y, w, acc.w);
}

// ---- aggregation conv1: warp per node, 128 ch fp16 (uint2/lane), +b1, relu ----
__global__ __launch_bounds__(256) void k_agg1(const float* __restrict__ b) {
    int gw   = (blockIdx.x * blockDim.x + threadIdx.x) >> 5;
    int lane = threadIdx.x & 31;
    if (gw >= NN) return;
    int e  = g_colptr[gw];
    int s1 = g_colptr[gw + 1];
    const uint2* hp = (const uint2*)g_h16;
    float4 acc = make_float4(0.f, 0.f, 0.f, 0.f);
    for (; e + 4 <= s1; e += 4) {
        int2 e0 = __ldcs(&g_ew[e]);
        int2 e1 = __ldcs(&g_ew[e + 1]);
        int2 e2 = __ldcs(&g_ew[e + 2]);
        int2 e3 = __ldcs(&g_ew[e + 3]);
        uint2 u0 = __ldg(&hp[(size_t)e0.x * 32 + lane]);
        uint2 u1 = __ldg(&hp[(size_t)e1.x * 32 + lane]);
        uint2 u2 = __ldg(&hp[(size_t)e2.x * 32 + lane]);
        uint2 u3 = __ldg(&hp[(size_t)e3.x * 32 + lane]);
        fma4_h(acc, u0, __int_as_float(e0.y));
        fma4_h(acc, u1, __int_as_float(e1.y));
        fma4_h(acc, u2, __int_as_float(e2.y));
        fma4_h(acc, u3, __int_as_float(e3.y));
    }
    for (; e < s1; e++) {
        int2 ew = __ldcs(&g_ew[e]);
        uint2 u = __ldg(&hp[(size_t)ew.x * 32 + lane]);
        fma4_h(acc, u, __int_as_float(ew.y));
    }
    float4 bv = ((const float4*)b)[lane];
    acc.x = fmaxf(acc.x + bv.x, 0.f);
    acc.y = fmaxf(acc.y + bv.y, 0.f);
    acc.z = fmaxf(acc.z + bv.z, 0.f);
    acc.w = fmaxf(acc.w + bv.w, 0.f);
    ((float4*)g_a)[(size_t)gw * 32 + lane] = acc;
}

// ---- GEMM2 standalone: h2 = a @ W2 (fp16 out) ----
__global__ __launch_bounds__(256) void k_gemm2(const float* __restrict__ W2) {
    gemm_block<OC>(g_a, W2, g_h216, blockIdx.x);
}

// ---- aggregation conv2: warp per node, 64 ch fp16 (uint/lane), +b2 ----
__global__ __launch_bounds__(256) void k_agg2(const float* __restrict__ b,
                                              float* __restrict__ out) {
    int gw   = (blockIdx.x * blockDim.x + threadIdx.x) >> 5;
    int lane = threadIdx.x & 31;
    if (gw >= NN) return;
    int e  = g_colptr[gw];
    int s1 = g_colptr[gw + 1];
    const unsigned* hp = (const unsigned*)g_h216;
    float2 acc = make_float2(0.f, 0.f);
    for (; e + 4 <= s1; e += 4) {
        int2 e0 = __ldcs(&g_ew[e]);
        int2 e1 = __ldcs(&g_ew[e + 1]);
        int2 e2 = __ldcs(&g_ew[e + 2]);
        int2 e3 = __ldcs(&g_ew[e + 3]);
        unsigned u0 = __ldg(&hp[(size_t)e0.x * 32 + lane]);
        unsigned u1 = __ldg(&hp[(size_t)e1.x * 32 + lane]);
        unsigned u2 = __ldg(&hp[(size_t)e2.x * 32 + lane]);
        unsigned u3 = __ldg(&hp[(size_t)e3.x * 32 + lane]);
        float2 f0 = __half22float2(*(__half2*)&u0);
        float2 f1 = __half22float2(*(__half2*)&u1);
        float2 f2 = __half22float2(*(__half2*)&u2);
        float2 f3 = __half22float2(*(__half2*)&u3);
        float w0 = __int_as_float(e0.y), w1 = __int_as_float(e1.y);
        float w2 = __int_as_float(e2.y), w3 = __int_as_float(e3.y);
        acc.x = fmaf(f0.x, w0, acc.x); acc.y = fmaf(f0.y, w0, acc.y);
        acc.x = fmaf(f1.x, w1, acc.x); acc.y = fmaf(f1.y, w1, acc.y);
        acc.x = fmaf(f2.x, w2, acc.x); acc.y = fmaf(f2.y, w2, acc.y);
        acc.x = fmaf(f3.x, w3, acc.x); acc.y = fmaf(f3.y, w3, acc.y);
    }
    for (; e < s1; e++) {
        int2 ew = __ldcs(&g_ew[e]);
        unsigned u = __ldg(&hp[(size_t)ew.x * 32 + lane]);
        float2 f = __half22float2(*(__half2*)&u);
        float w = __int_as_float(ew.y);
        acc.x = fmaf(f.x, w, acc.x); acc.y = fmaf(f.y, w, acc.y);
    }
    float2 bv = ((const float2*)b)[lane];
    acc.x += bv.x;
    acc.y += bv.y;
    ((float2*)out)[(size_t)gw * 32 + lane] = acc;
}

extern "C" void kernel_launch(void* const* d_in, const int* in_sizes, int n_in,
                              void* d_out, int out_size) {
    const float* x  = (const float*)d_in[0];
    const void*  ei = d_in[1];
    const float* W1 = (const float*)d_in[2];
    const float* b1 = (const float*)d_in[3];
    const float* W2 = (const float*)d_in[4];
    const float* b2 = (const float*)d_in[5];
    float* out = (float*)d_out;

    const int TB = 256;
    k_init<<<(NN + TB - 1) / TB, TB>>>((const int*)ei);
    k_fatA<<<CB + GBH, TB>>>(x, W1, ei);             // {count+rank} ∥ GEMM1 first half
    k_scanA<<<SB, 1024>>>();                         // block-local scan + dinv
    k_scanB<<<1, 128>>>();                           // scan of block totals
    k_scanC<<<SB, 1024>>>();                         // add offsets
    k_fatB<<<BB + (GB1 - GBH), TB>>>(x, W1, ei);     // CSR fill ∥ GEMM1 second half
    k_agg1<<<(NN * 32 + TB - 1) / TB, TB>>>(b1);     // S·h + b1, relu
    k_gemm2<<<GB1, TB>>>(W2);                        // a @ W2 -> fp16
    k_agg2<<<(NN * 32 + TB - 1) / TB, TB>>>(b2, out);// S·h2 + b2
}

// round 9
// speedup vs baseline: 2.1680x; 1.0409x over previous
#include <cuda_runtime.h>
#include <cuda_fp16.h>
#include <math.h>

#define NN 100000
#define EE 1600000
#define KC 128      // IN_C and HID (both 128)
#define HIDC 128
#define OC 64

#define GB1 ((NN + 127) / 128)   // 782 gemm tile blocks total
#define GBH 391                  // tiles in fatA (rest in fatB)
#define CB  146                  // count blocks in fatA
#define BB  160                  // build blocks in fatB
#define SB  ((NN + 1023) / 1024) // 98 scan blocks

// ---- device scratch (no allocations allowed) ----
__device__ int    g_deg[NN];
__device__ float  g_dinv[NN];
__device__ int    g_colptr[NN + 1];   // block-local exclusive prefixes (+boff at use)
__device__ int    g_rank[EE];         // within-bucket rank per edge
__device__ int    g_btot[SB];
__device__ int    g_boff[SB];
__device__ int    g_scancnt;
__device__ int2   g_ew[EE];                   // (src, weight bits) interleaved
__device__ __half g_h16 [(size_t)NN * HIDC];  // x @ W1          (fp16)
__device__ float  g_a   [(size_t)NN * HIDC];  // relu(agg1 + b1) (fp32)
__device__ __half g_h216[(size_t)NN * OC];    // g_a @ W2        (fp16)
__device__ int    g_is64;

__device__ __forceinline__ int edge_at(const void* ei, size_t idx, int is64) {
    if (is64) return (int)((const long long*)ei)[idx];
    return ((const int*)ei)[idx];
}

// ---- packed f32x2 helpers ----
__device__ __forceinline__ void fma2(unsigned long long& acc,
                                     unsigned long long a,
                                     unsigned long long b) {
    asm("fma.rn.f32x2 %0, %1, %2, %3;" : "=l"(acc) : "l"(a), "l"(b), "l"(acc));
}
__device__ __forceinline__ unsigned long long bcast2(float v) {
    unsigned long long r;
    asm("mov.b64 %0, {%1, %1};" : "=l"(r) : "f"(v));
    return r;
}

// ---- init: zero degrees + scan counter + dtype detect (block 0) ----
__global__ void k_init(const int* __restrict__ ei32) {
    int i = blockIdx.x * blockDim.x + threadIdx.x;
    if (i < NN) g_deg[i] = 0;
    if (i == 0) g_scancnt = 0;
    if (blockIdx.x == 0) {
        __shared__ int nz;
        if (threadIdx.x == 0) nz = 0;
        __syncthreads();
        for (int j = threadIdx.x; j < 4096; j += blockDim.x) {
            if (ei32[2 * j + 1] != 0) nz = 1;  // benign race
        }
        __syncthreads();
        if (threadIdx.x == 0) g_is64 = nz ? 0 : 1;
    }
}

// ---- double-buffered f32x2 GEMM tile:
// Y[128 x OUTC](fp16) = X[128,128](fp32) @ W[128,OUTC]; 256 thr, 8x(8|4)/thr.
// Accumulators paired along rows: acc2[p][j] = (row 2p, row 2p+1) of col j.
template <int OUTC>
__device__ __forceinline__ void gemm_block(const float* __restrict__ X,
                                           const float* __restrict__ W,
                                           __half* __restrict__ Y, int bx) {
    constexpr int TN = (OUTC == 128) ? 8 : 4;
    __shared__ float xs[2][8 * 132];   // [kk*132 + r], padded
    __shared__ float ws[2][8 * OUTC];  // [kk*OUTC + c]
    const int tid  = threadIdx.x;
    const int row0 = bx * 128;
    const int tx = tid & 15, ty = tid >> 4;
    const int tr = ty * 8,   tc = tx * TN;
    const int lr = tid >> 1, lk = (tid & 1) * 4;
    const int wk = tid >> 5;
    const int wc4 = (tid & 31) * 4, wc2 = (tid & 31) * 2;
    const int gr = row0 + lr;

    unsigned long long acc2[4][TN];
#pragma unroll
    for (int p = 0; p < 4; p++)
#pragma unroll
        for (int j = 0; j < TN; j++) acc2[p][j] = 0ull;

    // prologue: load chunk 0 into buffer 0
    float4 xv = make_float4(0.f, 0.f, 0.f, 0.f);
    if (gr < NN) xv = __ldcs((const float4*)&X[(size_t)gr * KC + lk]);
    float4 wv4; float2 wv2;
    if (OUTC == 128) wv4 = *(const float4*)&W[(size_t)wk * OUTC + wc4];
    else             wv2 = *(const float2*)&W[(size_t)wk * OUTC + wc2];
    xs[0][(lk + 0) * 132 + lr] = xv.x;
    xs[0][(lk + 1) * 132 + lr] = xv.y;
    xs[0][(lk + 2) * 132 + lr] = xv.z;
    xs[0][(lk + 3) * 132 + lr] = xv.w;
    if (OUTC == 128) *(float4*)&ws[0][wk * OUTC + wc4] = wv4;
    else             *(float2*)&ws[0][wk * OUTC + wc2] = wv2;
    __syncthreads();

    int buf = 0;
    for (int kb = 0; kb < KC; kb += 8) {
        const bool more = (kb + 8) < KC;
        if (more) {
            xv = make_float4(0.f, 0.f, 0.f, 0.f);
            if (gr < NN) xv = __ldcs((const float4*)&X[(size_t)gr * KC + kb + 8 + lk]);
            if (OUTC == 128) wv4 = *(const float4*)&W[(size_t)(kb + 8 + wk) * OUTC + wc4];
            else             wv2 = *(const float2*)&W[(size_t)(kb + 8 + wk) * OUTC + wc2];
        }
#pragma unroll
        for (int kk = 0; kk < 8; kk++) {
            unsigned long long xp[4];
            *(uint4*)&xp[0] = *(const uint4*)&xs[buf][kk * 132 + tr];
            *(uint4*)&xp[2] = *(const uint4*)&xs[buf][kk * 132 + tr + 4];
            float wr[TN];
#pragma unroll
            for (int j = 0; j < TN; j += 4)
                *(float4*)&wr[j] = *(const float4*)&ws[buf][kk * OUTC + tc + j];
            unsigned long long wp[TN];
#pragma unroll
            for (int j = 0; j < TN; j++) wp[j] = bcast2(wr[j]);
#pragma unroll
            for (int p = 0; p < 4; p++)
#pragma unroll
                for (int j = 0; j < TN; j++)
                    fma2(acc2[p][j], xp[p], wp[j]);
        }
        if (more) {
            int nb = buf ^ 1;
            xs[nb][(lk + 0) * 132 + lr] = xv.x;
            xs[nb][(lk + 1) * 132 + lr] = xv.y;
            xs[nb][(lk + 2) * 132 + lr] = xv.z;
            xs[nb][(lk + 3) * 132 + lr] = xv.w;
            if (OUTC == 128) *(float4*)&ws[nb][wk * OUTC + wc4] = wv4;
            else             *(float2*)&ws[nb][wk * OUTC + wc2] = wv2;
        }
        __syncthreads();
        buf ^= 1;
    }
    // epilogue: unpack row-pairs, convert to fp16, store
#pragma unroll
    for (int p = 0; p < 4; p++) {
        float lo[TN], hi[TN];
#pragma unroll
        for (int j = 0; j < TN; j++) {
            float2 v = *(float2*)&acc2[p][j];
            lo[j] = v.x; hi[j] = v.y;
        }
        int r0w = row0 + tr + 2 * p;
        if (r0w < NN) {
            __half2 hb[TN / 2];
#pragma unroll
            for (int j = 0; j < TN; j += 2) hb[j / 2] = __floats2half2_rn(lo[j], lo[j + 1]);
            if (OUTC == 128) *(uint4*)&Y[(size_t)r0w * OUTC + tc] = *(uint4*)hb;
            else             *(uint2*)&Y[(size_t)r0w * OUTC + tc] = *(uint2*)hb;
        }
        int r1w = row0 + tr + 2 * p + 1;
        if (r1w < NN) {
            __half2 hb[TN / 2];
#pragma unroll
            for (int j = 0; j < TN; j += 2) hb[j / 2] = __floats2half2_rn(hi[j], hi[j + 1]);
            if (OUTC == 128) *(uint4*)&Y[(size_t)r1w * OUTC + tc] = *(uint4*)hb;
            else             *(uint2*)&Y[(size_t)r1w * OUTC + tc] = *(uint2*)hb;
        }
    }
}

// ---- fatA: blocks [0,CB) count degrees + record ranks; rest GEMM1 tiles [0,GBH)
__global__ __launch_bounds__(256) void k_fatA(const float* __restrict__ X,
                                              const float* __restrict__ W1,
                                              const void* __restrict__ ei) {
    if (blockIdx.x < CB) {
        int is64 = g_is64;
        int t = blockIdx.x * 256 + threadIdx.x;
        for (int e = t; e < EE; e += CB * 256) {
            int c = edge_at(ei, (size_t)EE + e, is64);
            g_rank[e] = atomicAdd(&g_deg[c], 1);
        }
    } else {
        gemm_block<HIDC>(X, W1, g_h16, blockIdx.x - CB);
    }
}

// ---- fused scan: block-local scan + dinv; last block scans block totals ----
__global__ __launch_bounds__(1024) void k_scan() {
    __shared__ int sh[1024];
    __shared__ bool amlast;
    int t = threadIdx.x;
    int i = blockIdx.x * 1024 + t;
    int d = 0;
    if (i < NN) {
        d = g_deg[i];
        g_dinv[i] = (d > 0) ? rsqrtf((float)d) : 0.0f;
    }
    sh[t] = d;
    __syncthreads();
    for (int off = 1; off < 1024; off <<= 1) {
        int v = 0;
        if (t >= off) v = sh[t - off];
        __syncthreads();
        if (t >= off) sh[t] += v;
        __syncthreads();
    }
    if (i < NN) g_colptr[i] = sh[t] - d;   // block-local exclusive prefix
    if (t == 1023) g_btot[blockIdx.x] = sh[1023];

    __threadfence();
    if (t == 0) amlast = (atomicAdd(&g_scancnt, 1) == gridDim.x - 1);
    __syncthreads();
    if (!amlast) return;

    // last block: exclusive scan of SB block totals
    int v = (t < SB) ? g_btot[t] : 0;
    if (t < 128) sh[t] = v;
    __syncthreads();
    for (int off = 1; off < 128; off <<= 1) {
        int u = 0;
        if (t >= off && t < 128) u = sh[t - off];
        __syncthreads();
        if (t >= off && t < 128) sh[t] += u;
        __syncthreads();
    }
    if (t < SB) g_boff[t] = sh[t] - v;
    if (t == SB - 1) g_colptr[NN] = v;  // + g_boff[SB-1] at use = grand total
}

// ---- fatB: blocks [0,BB) atomic-free CSR fill; rest GEMM1 tiles [GBH,GB1) ----
__global__ __launch_bounds__(256) void k_fatB(const float* __restrict__ X,
                                              const float* __restrict__ W1,
                                              const void* __restrict__ ei) {
    if (blockIdx.x < BB) {
        int is64 = g_is64;
        int t = blockIdx.x * 256 + threadIdx.x;
        for (int e = t; e < EE; e += BB * 256) {
            int r = edge_at(ei, (size_t)e, is64);
            int c = edge_at(ei, (size_t)EE + e, is64);
            float w = g_dinv[r] * g_dinv[c];
            int pos = g_colptr[c] + g_boff[c >> 10] + g_rank[e];
            g_ew[pos] = make_int2(r, __float_as_int(w));
        }
    } else {
        gemm_block<HIDC>(X, W1, g_h16, GBH + blockIdx.x - BB);
    }
}

__device__ __forceinline__ void fma4_h(float4& acc, uint2 u, float w) {
    float2 f0 = __half22float2(*(__half2*)&u.x);
    float2 f1 = __half22float2(*(__half2*)&u.y);
    acc.x = fmaf(f0.x, w, acc.x);
    acc.y = fmaf(f0.y, w, acc.y);
    acc.z = fmaf(f1.x, w, acc.z);
    acc.w = fmaf(f1.y, w, acc.w);
}

// ---- aggregation conv1: warp per node, 128 ch fp16 (uint2/lane), +b1, relu ----
__global__ __launch_bounds__(256) void k_agg1(const float* __restrict__ b) {
    int gw   = (blockIdx.x * blockDim.x + threadIdx.x) >> 5;
    int lane = threadIdx.x & 31;
    if (gw >= NN) return;
    int e  = g_colptr[gw] + g_boff[gw >> 10];
    int s1 = g_colptr[gw + 1] + g_boff[(gw + 1) >> 10];
    const uint2* hp = (const uint2*)g_h16;
    float4 acc = make_float4(0.f, 0.f, 0.f, 0.f);
    for (; e + 4 <= s1; e += 4) {
        int2 e0 = __ldcs(&g_ew[e]);
        int2 e1 = __ldcs(&g_ew[e + 1]);
        int2 e2 = __ldcs(&g_ew[e + 2]);
        int2 e3 = __ldcs(&g_ew[e + 3]);
        uint2 u0 = __ldg(&hp[(size_t)e0.x * 32 + lane]);
        uint2 u1 = __ldg(&hp[(size_t)e1.x * 32 + lane]);
        uint2 u2 = __ldg(&hp[(size_t)e2.x * 32 + lane]);
        uint2 u3 = __ldg(&hp[(size_t)e3.x * 32 + lane]);
        fma4_h(acc, u0, __int_as_float(e0.y));
        fma4_h(acc, u1, __int_as_float(e1.y));
        fma4_h(acc, u2, __int_as_float(e2.y));
        fma4_h(acc, u3, __int_as_float(e3.y));
    }
    for (; e < s1; e++) {
        int2 ew = __ldcs(&g_ew[e]);
        uint2 u = __ldg(&hp[(size_t)ew.x * 32 + lane]);
        fma4_h(acc, u, __int_as_float(ew.y));
    }
    float4 bv = ((const float4*)b)[lane];
    acc.x = fmaxf(acc.x + bv.x, 0.f);
    acc.y = fmaxf(acc.y + bv.y, 0.f);
    acc.z = fmaxf(acc.z + bv.z, 0.f);
    acc.w = fmaxf(acc.w + bv.w, 0.f);
    ((float4*)g_a)[(size_t)gw * 32 + lane] = acc;
}

// ---- GEMM2 standalone: h2 = a @ W2 (fp16 out) ----
__global__ __launch_bounds__(256) void k_gemm2(const float* __restrict__ W2) {
    gemm_block<OC>(g_a, W2, g_h216, blockIdx.x);
}

// ---- aggregation conv2: warp per node, 64 ch fp16 (uint/lane), +b2 ----
__global__ __launch_bounds__(256) void k_agg2(const float* __restrict__ b,
                                              float* __restrict__ out) {
    int gw   = (blockIdx.x * blockDim.x + threadIdx.x) >> 5;
    int lane = threadIdx.x & 31;
    if (gw >= NN) return;
    int e  = g_colptr[gw] + g_boff[gw >> 10];
    int s1 = g_colptr[gw + 1] + g_boff[(gw + 1) >> 10];
    const unsigned* hp = (const unsigned*)g_h216;
    float2 acc = make_float2(0.f, 0.f);
    for (; e + 4 <= s1; e += 4) {
        int2 e0 = __ldcs(&g_ew[e]);
        int2 e1 = __ldcs(&g_ew[e + 1]);
        int2 e2 = __ldcs(&g_ew[e + 2]);
        int2 e3 = __ldcs(&g_ew[e + 3]);
        unsigned u0 = __ldg(&hp[(size_t)e0.x * 32 + lane]);
        unsigned u1 = __ldg(&hp[(size_t)e1.x * 32 + lane]);
        unsigned u2 = __ldg(&hp[(size_t)e2.x * 32 + lane]);
        unsigned u3 = __ldg(&hp[(size_t)e3.x * 32 + lane]);
        float2 f0 = __half22float2(*(__half2*)&u0);
        float2 f1 = __half22float2(*(__half2*)&u1);
        float2 f2 = __half22float2(*(__half2*)&u2);
        float2 f3 = __half22float2(*(__half2*)&u3);
        float w0 = __int_as_float(e0.y), w1 = __int_as_float(e1.y);
        float w2 = __int_as_float(e2.y), w3 = __int_as_float(e3.y);
        acc.x = fmaf(f0.x, w0, acc.x); acc.y = fmaf(f0.y, w0, acc.y);
        acc.x = fmaf(f1.x, w1, acc.x); acc.y = fmaf(f1.y, w1, acc.y);
        acc.x = fmaf(f2.x, w2, acc.x); acc.y = fmaf(f2.y, w2, acc.y);
        acc.x = fmaf(f3.x, w3, acc.x); acc.y = fmaf(f3.y, w3, acc.y);
    }
    for (; e < s1; e++) {
        int2 ew = __ldcs(&g_ew[e]);
        unsigned u = __ldg(&hp[(size_t)ew.x * 32 + lane]);
        float2 f = __half22float2(*(__half2*)&u);
        float w = __int_as_float(ew.y);
        acc.x = fmaf(f.x, w, acc.x); acc.y = fmaf(f.y, w, acc.y);
    }
    float2 bv = ((const float2*)b)[lane];
    acc.x += bv.x;
    acc.y += bv.y;
    ((float2*)out)[(size_t)gw * 32 + lane] = acc;
}

extern "C" void kernel_launch(void* const* d_in, const int* in_sizes, int n_in,
                              void* d_out, int out_size) {
    const float* x  = (const float*)d_in[0];
    const void*  ei = d_in[1];
    const float* W1 = (const float*)d_in[2];
    const float* b1 = (const float*)d_in[3];
    const float* W2 = (const float*)d_in[4];
    const float* b2 = (const float*)d_in[5];
    float* out = (float*)d_out;

    const int TB = 256;
    k_init<<<(NN + TB - 1) / TB, TB>>>((const int*)ei);
    k_fatA<<<CB + GBH, TB>>>(x, W1, ei);             // {count+rank} ∥ GEMM1 first half
    k_scan<<<SB, 1024>>>();                          // fused scan (last-block totals)
    k_fatB<<<BB + (GB1 - GBH), TB>>>(x, W1, ei);     // CSR fill ∥ GEMM1 second half
    k_agg1<<<(NN * 32 + TB - 1) / TB, TB>>>(b1);     // S·h + b1, relu
    k_gemm2<<<GB1, TB>>>(W2);                        // a @ W2 -> fp16 (f32x2 pipe)
    k_agg2<<<(NN * 32 + TB - 1) / TB, TB>>>(b2, out);// S·h2 + b2
}